// round 13
// baseline (speedup 1.0000x reference)
#include <cuda_runtime.h>
#include <cuda_bf16.h>
#include <cstdint>

#define Dv 512
#define Rv 64
#define TM 128
#define NTHREADS 256

// ---------------------------------------------------------------------------
// Device scratch
// ---------------------------------------------------------------------------
__device__ float g_G0p[4 * 4096];  // Gram partials (4 d-quarters)
// Pre-packed bf16 hi/lo operand tiles, 128B rows, SW128-swizzled
__device__ __align__(16) __nv_bfloat16 g_Abh[8 * 64 * 64];   // chunk c: [r][kk]
__device__ __align__(16) __nv_bfloat16 g_Abl[8 * 64 * 64];
__device__ __align__(16) __nv_bfloat16 g_Vbh[8 * 64 * 64];   // n-tile j: [n64][r64]
__device__ __align__(16) __nv_bfloat16 g_Vbl[8 * 64 * 64];

// ---------------------------------------------------------------------------
// Helpers
// ---------------------------------------------------------------------------
#define SWZ(o) ((o) ^ (((o) >> 3) & 0x70))

__device__ __forceinline__ uint32_t smem_to_u32(const void* p) {
    uint32_t a;
    asm("{ .reg .u64 t; cvta.to.shared.u64 t, %1; cvt.u32.u64 %0, t; }" : "=r"(a) : "l"(p));
    return a;
}
__device__ __forceinline__ void ldsm4(uint32_t* r, uint32_t addr) {
    asm volatile("ldmatrix.sync.aligned.m8n8.x4.shared.b16 {%0,%1,%2,%3}, [%4];"
                 : "=r"(r[0]), "=r"(r[1]), "=r"(r[2]), "=r"(r[3]) : "r"(addr));
}
__device__ __forceinline__ void mma16816(float* c, const uint32_t* a,
                                         uint32_t b0, uint32_t b1) {
    asm volatile("mma.sync.aligned.m16n8k16.row.col.f32.bf16.bf16.f32 "
                 "{%0,%1,%2,%3}, {%4,%5,%6,%7}, {%8,%9}, {%0,%1,%2,%3};"
                 : "+f"(c[0]), "+f"(c[1]), "+f"(c[2]), "+f"(c[3])
                 : "r"(a[0]), "r"(a[1]), "r"(a[2]), "r"(a[3]), "r"(b0), "r"(b1));
}
__device__ __forceinline__ float2 lds64(uint32_t a) {
    float2 v;
    asm volatile("ld.shared.v2.f32 {%0,%1}, [%2];" : "=f"(v.x), "=f"(v.y) : "r"(a));
    return v;
}
__device__ __forceinline__ void cpasync16(uint32_t dst, const void* src) {
    asm volatile("cp.async.cg.shared.global [%0], [%1], 16;"
                 :: "r"(dst), "l"(src) : "memory");
}
#define CP_COMMIT() asm volatile("cp.async.commit_group;" ::: "memory")
#define CP_WAIT(N)  asm volatile("cp.async.wait_group %0;" :: "n"(N) : "memory")

__device__ __forceinline__ uint32_t cvt2(float f0, float f1) {
    uint32_t r;
    asm("cvt.rn.bf16x2.f32 %0, %1, %2;" : "=r"(r) : "f"(f1), "f"(f0));
    return r;
}
__device__ __forceinline__ float bl(uint32_t h) { return __uint_as_float(h << 16); }
__device__ __forceinline__ float bh(uint32_t h) { return __uint_as_float(h & 0xFFFF0000u); }

// ---------------------------------------------------------------------------
// Precompute 1: Gram partials. 256 blocks (64 j x 4 d-quarters) x 256 thr.
// ---------------------------------------------------------------------------
__global__ __launch_bounds__(256) void k_gram(const float* __restrict__ P) {
    __shared__ float red[4][64];
    int bid = blockIdx.x;
    int j = bid & 63, q = bid >> 6;
    int k = threadIdx.x & 63, g = threadIdx.x >> 6;
    const float* p = P + (q * 128 + g * 32) * 64;
    float a[8] = {};
    #pragma unroll
    for (int d = 0; d < 32; d += 8) {
        #pragma unroll
        for (int e = 0; e < 8; e++)
            a[e] += __ldg(p + (d + e) * 64 + j) * __ldg(p + (d + e) * 64 + k);
    }
    red[g][k] = ((a[0] + a[1]) + (a[2] + a[3])) + ((a[4] + a[5]) + (a[6] + a[7]));
    __syncthreads();
    if (g == 0)
        g_G0p[q * 4096 + j * 64 + k] =
            (red[0][k] + red[1][k]) + (red[2][k] + red[3][k]);
}

// ---------------------------------------------------------------------------
// Precompute 2: 16 blocks x 512 thr.
//  blocks 0-7:  scan back-sub + pack A chunk c=bid
//  blocks 8-15: pack V n-tile jn=bid-8 (64 rows x 64 r)
// ---------------------------------------------------------------------------
#define PR_RV  0            // 64
#define PR_M   64           // 64*65
#define PR_W2  4224         // 64*65
#define PR_SP  8384         // 64*68
#define PR_PV  64           // 64*65 (V path overlaps M)
#define PR_FLOATS 12736

__global__ __launch_bounds__(512) void k_pack(const float* __restrict__ P) {
    extern __shared__ float sm[];
    int bid = blockIdx.x, tid = threadIdx.x, w = tid >> 5, lane = tid & 31;

    if (tid < 64) {
        float s = g_G0p[tid * 65] + g_G0p[4096 + tid * 65]
                + g_G0p[8192 + tid * 65] + g_G0p[12288 + tid * 65];
        sm[PR_RV + tid] = rsqrtf(s);
    }
    __syncthreads();

    if (bid < 8) {
        int c = bid;
        for (int idx = tid; idx < 4096; idx += 512) {
            int i = idx >> 6, l = idx & 63;
            float gv = g_G0p[idx] + g_G0p[4096 + idx]
                     + g_G0p[8192 + idx] + g_G0p[12288 + idx];
            sm[PR_M + i * 65 + l] = 2.f * gv * sm[PR_RV + i] * sm[PR_RV + l];
        }
        for (int idx = tid; idx < 4096; idx += 512)
            sm[PR_SP + (idx >> 6) * 68 + (idx & 63)] = P[c * 4096 + idx];
        __syncthreads();

        // scan back-substitution: warp w solves cols {w, w+16, w+32, w+48}
        {
            float S0[4] = {0.f, 0.f, 0.f, 0.f};
            float S1[4] = {0.f, 0.f, 0.f, 0.f};
            float wv0[4] = {0.f, 0.f, 0.f, 0.f};
            float wv1[4] = {0.f, 0.f, 0.f, 0.f};
            for (int i = 63; i >= 0; --i) {
                float m0 = sm[PR_M + i * 65 + lane];
                float m1 = sm[PR_M + i * 65 + lane + 32];
                #pragma unroll
                for (int q = 0; q < 4; q++) {
                    int cq = w + 16 * q;
                    float sown = (i < 32) ? S0[q] : S1[q];
                    float s_i = __shfl_sync(0xFFFFFFFFu, sown, i & 31);
                    float wi = (i > cq) ? 0.f : ((i == cq) ? 1.f : -s_i);
                    if (lane == i)      wv0[q] = wi;
                    if (lane + 32 == i) wv1[q] = wi;
                    if (lane < i)       S0[q] += m0 * wi;
                    if (lane + 32 < i)  S1[q] += m1 * wi;
                }
            }
            #pragma unroll
            for (int q = 0; q < 4; q++) {
                int cq = w + 16 * q;
                sm[PR_W2 + lane * 65 + cq]        = 2.f * sm[PR_RV + lane] * wv0[q];
                sm[PR_W2 + (lane + 32) * 65 + cq] = 2.f * sm[PR_RV + lane + 32] * wv1[q];
            }
        }
        __syncthreads();

        int rr = tid & 63, kb = (tid >> 6) << 3;
        float pacc[8] = {};
        #pragma unroll 4
        for (int jj = 0; jj < 64; jj++) {
            float wv = sm[PR_W2 + jj * 65 + rr];
            #pragma unroll
            for (int e = 0; e < 8; e++)
                pacc[e] += sm[PR_SP + (kb + e) * 68 + jj] * wv;
        }
        #pragma unroll
        for (int e = 0; e < 8; e++) {
            float v = pacc[e];
            __nv_bfloat16 h = __float2bfloat16_rn(v);
            float lo = v - __bfloat162float(h);
            uint32_t off = c * 8192 + SWZ((uint32_t)(rr * 128 + (kb + e) * 2));
            *(__nv_bfloat16*)((char*)g_Abh + off) = h;
            *(__nv_bfloat16*)((char*)g_Abl + off) = __float2bfloat16_rn(lo);
        }
    } else {
        int jn = bid - 8;      // 64-row V tile
        for (int idx = tid; idx < 4096; idx += 512)
            sm[PR_PV + (idx >> 6) * 65 + (idx & 63)] = P[jn * 4096 + idx];
        __syncthreads();
        for (int idx = tid; idx < 4096; idx += 512) {
            int n = idx >> 6, r = idx & 63;
            float v = sm[PR_PV + n * 65 + r] * sm[PR_RV + r];
            __nv_bfloat16 h = __float2bfloat16_rn(v);
            float lo = v - __bfloat162float(h);
            uint32_t off = jn * 8192 + SWZ((uint32_t)(n * 128 + r * 2));
            *(__nv_bfloat16*)((char*)g_Vbh + off) = h;
            *(__nv_bfloat16*)((char*)g_Vbl + off) = __float2bfloat16_rn(lo);
        }
    }
}

// ---------------------------------------------------------------------------
// Main kernel: 64KB smem -> 3 CTA/SM. Phase 2 in 8 n-tiles of 64 (z = 32 regs).
// smem:
//   [0,     32768)  stage: 8 warp blocks x 4KB   / phase2 V slots 0,1 (16KB ea)
//   [32768, 65536)  A ping(16K)+pong(16K)        / phase2 V slots 2,3
// ---------------------------------------------------------------------------
#define OFF_STAGE 0
#define OFF_A0    32768
#define OFF_A1    49152
#define SMEM_BYTES 65536

__global__ __launch_bounds__(NTHREADS, 3) void k_gemm(const float* __restrict__ x,
                                                      float* __restrict__ out,
                                                      const float* __restrict__ sldj,
                                                      float* __restrict__ outSldj) {
    extern __shared__ char smem[];
    uint32_t sb = smem_to_u32(smem);

    int tid = threadIdx.x, wid = tid >> 5, lane = tid & 31;
    int m0 = blockIdx.x * TM;
    int mw = wid << 4;

    // B-side ldsm addressing (tiles with 128B rows, SW128)
    uint32_t lrow = lane & 15;
    uint32_t lcolb = (lane >> 4) << 4;
    uint32_t xwB = (lrow & 7) << 4;

    // A-side (warp-private fp32 stage)
    int r = lane >> 2;
    uint32_t rot = (uint32_t)(r & 7) << 5;
    uint32_t o3 = (uint32_t)(lane & 1) * 8;
    uint32_t sbStageW = sb + OFF_STAGE + wid * 4096;
    uint32_t rowbase = sbStageW + r * 256 + o3;
    int cpair = (lane >> 1) & 1;

    auto issueA = [&](int c, uint32_t buf) {
        const char* srch = (const char*)g_Abh + c * 8192;
        const char* srcl = (const char*)g_Abl + c * 8192;
        for (int idx = tid; idx < 512; idx += NTHREADS) {
            cpasync16(buf + idx * 16, srch + idx * 16);
            cpasync16(buf + 8192 + idx * 16, srcl + idx * 16);
        }
    };
    auto issueXown = [&](int c) {
        #pragma unroll
        for (int u = 0; u < 8; u++) {
            int unit = lane + u * 32;
            int lr = unit >> 4, i16 = unit & 15;
            uint32_t dst = sbStageW + lr * 256 +
                           (((uint32_t)(i16 * 16)) ^ ((uint32_t)(lr & 7) << 5));
            const char* src = (const char*)(x + (size_t)(m0 + mw + lr) * Dv
                                            + c * 64 + i16 * 4);
            cpasync16(dst, src);
        }
    };
    auto issueV = [&](int j, uint32_t slot) {      // hi 8K at slot, lo 8K after
        const char* srch = (const char*)g_Vbh + j * 8192;
        const char* srcl = (const char*)g_Vbl + j * 8192;
        for (int idx = tid; idx < 512; idx += NTHREADS) {
            cpasync16(slot + idx * 16, srch + idx * 16);
            cpasync16(slot + 8192 + idx * 16, srcl + idx * 16);
        }
    };

    float acc[8][4];
    #pragma unroll
    for (int i = 0; i < 8; i++)
        acc[i][0] = acc[i][1] = acc[i][2] = acc[i][3] = 0.f;

    // prologue: A0 + own X0
    issueA(0, sb + OFF_A0);
    issueXown(0);
    CP_COMMIT();

    // ================= Phase 1: Y = X A  (8 k-chunks of 64) =================
    for (int c = 0; c < 8; c++) {
        CP_WAIT(0);
        __syncthreads();
        if (c < 7) { issueA(c + 1, sb + (((c + 1) & 1) ? OFF_A1 : OFF_A0)); CP_COMMIT(); }

        uint32_t bufAh = sb + ((c & 1) ? OFF_A1 : OFF_A0);
        uint32_t bufAl = bufAh + 8192;
        #pragma unroll
        for (int ks = 0; ks < 4; ks++) {
            int b0 = 4 * ks + cpair;
            uint32_t u0 = ((uint32_t)(b0 * 16)) ^ rot;
            uint32_t u1 = ((uint32_t)((b0 + 2) * 16)) ^ rot;
            float2 fa = lds64(rowbase + u0);
            float2 fb = lds64(rowbase + 2048 + u0);
            float2 fc = lds64(rowbase + u1);
            float2 fd = lds64(rowbase + 2048 + u1);
            uint32_t ah[4], al[4];
            ah[0] = cvt2(fa.x, fa.y); al[0] = cvt2(fa.x - bl(ah[0]), fa.y - bh(ah[0]));
            ah[1] = cvt2(fb.x, fb.y); al[1] = cvt2(fb.x - bl(ah[1]), fb.y - bh(ah[1]));
            ah[2] = cvt2(fc.x, fc.y); al[2] = cvt2(fc.x - bl(ah[2]), fc.y - bh(ah[2]));
            ah[3] = cvt2(fd.x, fd.y); al[3] = cvt2(fd.x - bl(ah[3]), fd.y - bh(ah[3]));

            uint32_t ic = (lcolb + ks * 32) ^ xwB;
            #pragma unroll
            for (int p = 0; p < 4; p++) {
                uint32_t ro = (lrow + p * 16) * 128;
                uint32_t bhr[4], blr[4];
                ldsm4(bhr, bufAh + ro + ic);
                ldsm4(blr, bufAl + ro + ic);
                mma16816(acc[2 * p],     ah, bhr[0], bhr[2]);
                mma16816(acc[2 * p],     ah, blr[0], blr[2]);
                mma16816(acc[2 * p],     al, bhr[0], bhr[2]);
                mma16816(acc[2 * p + 1], ah, bhr[1], bhr[3]);
                mma16816(acc[2 * p + 1], ah, blr[1], blr[3]);
                mma16816(acc[2 * p + 1], al, bhr[1], bhr[3]);
            }
        }
        if (c < 7) { issueXown(c + 1); CP_COMMIT(); }
    }
    __syncthreads();                     // phase 1 done: all 64KB free

    // prologue for phase 2: V0..V3 into the 4 slots (4 groups)
    issueV(0, sb + 0);     CP_COMMIT();
    issueV(1, sb + 16384); CP_COMMIT();
    issueV(2, sb + 32768); CP_COMMIT();
    issueV(3, sb + 49152); CP_COMMIT();

    // ======= Y: register repack acc (C-frag) -> phase-2 A-frags (hi/lo) =====
    uint32_t yh[4][4], yl[4][4];
    #pragma unroll
    for (int kb = 0; kb < 4; kb++) {
        uint32_t h;
        h = cvt2(acc[2*kb][0],   acc[2*kb][1]);   yh[kb][0] = h;
        yl[kb][0] = cvt2(acc[2*kb][0] - bl(h),    acc[2*kb][1] - bh(h));
        h = cvt2(acc[2*kb][2],   acc[2*kb][3]);   yh[kb][1] = h;
        yl[kb][1] = cvt2(acc[2*kb][2] - bl(h),    acc[2*kb][3] - bh(h));
        h = cvt2(acc[2*kb+1][0], acc[2*kb+1][1]); yh[kb][2] = h;
        yl[kb][2] = cvt2(acc[2*kb+1][0] - bl(h),  acc[2*kb+1][1] - bh(h));
        h = cvt2(acc[2*kb+1][2], acc[2*kb+1][3]); yh[kb][3] = h;
        yl[kb][3] = cvt2(acc[2*kb+1][2] - bl(h),  acc[2*kb+1][3] - bh(h));
    }

    // ====== Phase 2: Z = Y V^T over 8 n-tiles of 64, rolling 4 slots ========
    #pragma unroll
    for (int j = 0; j < 8; j++) {
        // wait for V(j); allowed-incomplete = groups issued after it
        if (j == 0)      CP_WAIT(3);
        else if (j <= 5) CP_WAIT(2);
        else if (j == 6) CP_WAIT(1);
        else             CP_WAIT(0);
        __syncthreads();                 // all warps past j-1 -> slot (j-1)&3 free
        if (j >= 1 && j <= 4) {          // refill freed slot with V(j+3)
            issueV(j + 3, sb + (uint32_t)(((j - 1) & 3) * 16384));
            CP_COMMIT();
        }
        uint32_t bufVh = sb + (uint32_t)((j & 3) * 16384);
        uint32_t bufVl = bufVh + 8192;

        float z[8][4];
        #pragma unroll
        for (int i = 0; i < 8; i++)
            z[i][0] = z[i][1] = z[i][2] = z[i][3] = 0.f;

        #pragma unroll
        for (int ks = 0; ks < 4; ks++) {
            uint32_t ic = (lcolb + ks * 32) ^ xwB;
            #pragma unroll
            for (int p = 0; p < 4; p++) {
                uint32_t ro = (lrow + p * 16) * 128;
                uint32_t bhr[4], blr[4];
                ldsm4(bhr, bufVh + ro + ic);
                ldsm4(blr, bufVl + ro + ic);
                mma16816(z[2 * p],     yh[ks], bhr[0], bhr[2]);
                mma16816(z[2 * p],     yh[ks], blr[0], blr[2]);
                mma16816(z[2 * p],     yl[ks], bhr[0], bhr[2]);
                mma16816(z[2 * p + 1], yh[ks], bhr[1], bhr[3]);
                mma16816(z[2 * p + 1], yh[ks], blr[1], blr[3]);
                mma16816(z[2 * p + 1], yl[ks], bhr[1], bhr[3]);
            }
        }

        // epilogue: out = x - z for this 64-col tile
        int r0 = m0 + mw + (lane >> 2);
        const float* x0p = x + (size_t)r0 * Dv;
        const float* x1p = x0p + 8 * Dv;
        float* o0 = out + (size_t)r0 * Dv;
        float* o1 = o0 + 8 * Dv;
        int cbase = (j << 6) + ((lane & 3) << 1);
        #pragma unroll
        for (int nt = 0; nt < 8; nt++) {
            int cc = cbase + nt * 8;
            float2 a0 = *(const float2*)(x0p + cc);
            float2 a1 = *(const float2*)(x1p + cc);
            float2 w0 = make_float2(a0.x - z[nt][0], a0.y - z[nt][1]);
            float2 w1 = make_float2(a1.x - z[nt][2], a1.y - z[nt][3]);
            *(float2*)(o0 + cc) = w0;
            *(float2*)(o1 + cc) = w1;
        }
    }

    if (outSldj != nullptr && tid < TM) {
        outSldj[m0 + tid] = sldj[m0 + tid];
    }
}

extern "C" void kernel_launch(void* const* d_in, const int* in_sizes, int n_in,
                              void* d_out, int out_size) {
    const float* x    = (const float*)d_in[0];   // (B, D)
    const float* sldj = (const float*)d_in[1];   // (B,)
    const float* P    = (const float*)d_in[2];   // (D, R)
    int BD = in_sizes[0];
    int Bn = in_sizes[1];
    (void)n_in;
    float* out = (float*)d_out;
    float* osl = (out_size >= BD + Bn) ? (out + BD) : nullptr;

    k_gram<<<256, 256>>>(P);
    cudaFuncSetAttribute(k_pack, cudaFuncAttributeMaxDynamicSharedMemorySize,
                         PR_FLOATS * 4);
    k_pack<<<16, 512, PR_FLOATS * 4>>>(P);

    cudaFuncSetAttribute(k_gemm, cudaFuncAttributeMaxDynamicSharedMemorySize, SMEM_BYTES);
    k_gemm<<<Bn / TM, NTHREADS, SMEM_BYTES>>>(x, out, sldj, osl);
}

// round 14
// speedup vs baseline: 1.0403x; 1.0403x over previous
#include <cuda_runtime.h>
#include <cuda_bf16.h>
#include <cstdint>

#define Dv 512
#define Rv 64
#define TM 128
#define NTHREADS 256

// ---------------------------------------------------------------------------
// Device scratch
// ---------------------------------------------------------------------------
__device__ float g_G0p[4 * 4096];  // Gram partials (4 d-quarters)
// Pre-packed bf16 hi/lo operand tiles, 128B rows, SW128-swizzled
__device__ __align__(16) __nv_bfloat16 g_Abh[8 * 64 * 64];   // chunk c: [r][kk]
__device__ __align__(16) __nv_bfloat16 g_Abl[8 * 64 * 64];
__device__ __align__(16) __nv_bfloat16 g_Vbh[4 * 128 * 64];  // n-chunk j: [n][r]
__device__ __align__(16) __nv_bfloat16 g_Vbl[4 * 128 * 64];

// ---------------------------------------------------------------------------
// Helpers
// ---------------------------------------------------------------------------
#define SWZ(o) ((o) ^ (((o) >> 3) & 0x70))

__device__ __forceinline__ uint32_t smem_to_u32(const void* p) {
    uint32_t a;
    asm("{ .reg .u64 t; cvta.to.shared.u64 t, %1; cvt.u32.u64 %0, t; }" : "=r"(a) : "l"(p));
    return a;
}
__device__ __forceinline__ void ldsm4(uint32_t* r, uint32_t addr) {
    asm volatile("ldmatrix.sync.aligned.m8n8.x4.shared.b16 {%0,%1,%2,%3}, [%4];"
                 : "=r"(r[0]), "=r"(r[1]), "=r"(r[2]), "=r"(r[3]) : "r"(addr));
}
__device__ __forceinline__ void mma16816(float* c, const uint32_t* a,
                                         uint32_t b0, uint32_t b1) {
    asm volatile("mma.sync.aligned.m16n8k16.row.col.f32.bf16.bf16.f32 "
                 "{%0,%1,%2,%3}, {%4,%5,%6,%7}, {%8,%9}, {%0,%1,%2,%3};"
                 : "+f"(c[0]), "+f"(c[1]), "+f"(c[2]), "+f"(c[3])
                 : "r"(a[0]), "r"(a[1]), "r"(a[2]), "r"(a[3]), "r"(b0), "r"(b1));
}
__device__ __forceinline__ float2 lds64(uint32_t a) {
    float2 v;
    asm volatile("ld.shared.v2.f32 {%0,%1}, [%2];" : "=f"(v.x), "=f"(v.y) : "r"(a));
    return v;
}
__device__ __forceinline__ void cpasync16(uint32_t dst, const void* src) {
    asm volatile("cp.async.cg.shared.global [%0], [%1], 16;"
                 :: "r"(dst), "l"(src) : "memory");
}
#define CP_COMMIT() asm volatile("cp.async.commit_group;" ::: "memory")
#define CP_WAIT(N)  asm volatile("cp.async.wait_group %0;" :: "n"(N) : "memory")

__device__ __forceinline__ uint32_t cvt2(float f0, float f1) {
    uint32_t r;
    asm("cvt.rn.bf16x2.f32 %0, %1, %2;" : "=r"(r) : "f"(f1), "f"(f0));
    return r;
}
__device__ __forceinline__ float bl(uint32_t h) { return __uint_as_float(h << 16); }
__device__ __forceinline__ float bh(uint32_t h) { return __uint_as_float(h & 0xFFFF0000u); }

// ---------------------------------------------------------------------------
// Precompute 1: Gram partials. 256 blocks (64 j x 4 d-quarters) x 256 thr.
// ---------------------------------------------------------------------------
__global__ __launch_bounds__(256) void k_gram(const float* __restrict__ P) {
    __shared__ float red[4][64];
    int bid = blockIdx.x;
    int j = bid & 63, q = bid >> 6;
    int k = threadIdx.x & 63, g = threadIdx.x >> 6;
    const float* p = P + (q * 128 + g * 32) * 64;
    float a[8] = {};
    #pragma unroll
    for (int d = 0; d < 32; d += 8) {
        #pragma unroll
        for (int e = 0; e < 8; e++)
            a[e] += __ldg(p + (d + e) * 64 + j) * __ldg(p + (d + e) * 64 + k);
    }
    red[g][k] = ((a[0] + a[1]) + (a[2] + a[3])) + ((a[4] + a[5]) + (a[6] + a[7]));
    __syncthreads();
    if (g == 0)
        g_G0p[q * 4096 + j * 64 + k] =
            (red[0][k] + red[1][k]) + (red[2][k] + red[3][k]);
}

// ---------------------------------------------------------------------------
// Precompute 2: 12 blocks x 512 thr (scan back-sub, validated R11/R12).
// ---------------------------------------------------------------------------
#define PR_RV  0            // 64
#define PR_M   64           // 64*65
#define PR_W2  4224         // 64*65
#define PR_SP  8384         // 64*68
#define PR_PV  64           // 128*65 (V path overlaps M/W2)
#define PR_FLOATS 12736

__global__ __launch_bounds__(512) void k_pack(const float* __restrict__ P) {
    extern __shared__ float sm[];
    int bid = blockIdx.x, tid = threadIdx.x, w = tid >> 5, lane = tid & 31;

    if (tid < 64) {
        float s = g_G0p[tid * 65] + g_G0p[4096 + tid * 65]
                + g_G0p[8192 + tid * 65] + g_G0p[12288 + tid * 65];
        sm[PR_RV + tid] = rsqrtf(s);
    }
    __syncthreads();

    if (bid < 8) {
        int c = bid;
        for (int idx = tid; idx < 4096; idx += 512) {
            int i = idx >> 6, l = idx & 63;
            float gv = g_G0p[idx] + g_G0p[4096 + idx]
                     + g_G0p[8192 + idx] + g_G0p[12288 + idx];
            sm[PR_M + i * 65 + l] = 2.f * gv * sm[PR_RV + i] * sm[PR_RV + l];
        }
        for (int idx = tid; idx < 4096; idx += 512)
            sm[PR_SP + (idx >> 6) * 68 + (idx & 63)] = P[c * 4096 + idx];
        __syncthreads();

        // scan back-substitution: warp w solves cols {w, w+16, w+32, w+48}
        {
            float S0[4] = {0.f, 0.f, 0.f, 0.f};
            float S1[4] = {0.f, 0.f, 0.f, 0.f};
            float wv0[4] = {0.f, 0.f, 0.f, 0.f};
            float wv1[4] = {0.f, 0.f, 0.f, 0.f};
            for (int i = 63; i >= 0; --i) {
                float m0 = sm[PR_M + i * 65 + lane];
                float m1 = sm[PR_M + i * 65 + lane + 32];
                #pragma unroll
                for (int q = 0; q < 4; q++) {
                    int cq = w + 16 * q;
                    float sown = (i < 32) ? S0[q] : S1[q];
                    float s_i = __shfl_sync(0xFFFFFFFFu, sown, i & 31);
                    float wi = (i > cq) ? 0.f : ((i == cq) ? 1.f : -s_i);
                    if (lane == i)      wv0[q] = wi;
                    if (lane + 32 == i) wv1[q] = wi;
                    if (lane < i)       S0[q] += m0 * wi;
                    if (lane + 32 < i)  S1[q] += m1 * wi;
                }
            }
            #pragma unroll
            for (int q = 0; q < 4; q++) {
                int cq = w + 16 * q;
                sm[PR_W2 + lane * 65 + cq]        = 2.f * sm[PR_RV + lane] * wv0[q];
                sm[PR_W2 + (lane + 32) * 65 + cq] = 2.f * sm[PR_RV + lane + 32] * wv1[q];
            }
        }
        __syncthreads();

        int rr = tid & 63, kb = (tid >> 6) << 3;
        float pacc[8] = {};
        #pragma unroll 4
        for (int jj = 0; jj < 64; jj++) {
            float wv = sm[PR_W2 + jj * 65 + rr];
            #pragma unroll
            for (int e = 0; e < 8; e++)
                pacc[e] += sm[PR_SP + (kb + e) * 68 + jj] * wv;
        }
        #pragma unroll
        for (int e = 0; e < 8; e++) {
            float v = pacc[e];
            __nv_bfloat16 h = __float2bfloat16_rn(v);
            float lo = v - __bfloat162float(h);
            uint32_t off = c * 8192 + SWZ((uint32_t)(rr * 128 + (kb + e) * 2));
            *(__nv_bfloat16*)((char*)g_Abh + off) = h;
            *(__nv_bfloat16*)((char*)g_Abl + off) = __float2bfloat16_rn(lo);
        }
    } else {
        int jn = bid - 8;
        for (int idx = tid; idx < 8192; idx += 512)
            sm[PR_PV + (idx >> 6) * 65 + (idx & 63)] = P[jn * 8192 + idx];
        __syncthreads();
        for (int idx = tid; idx < 8192; idx += 512) {
            int n = idx >> 6, r = idx & 63;
            float v = sm[PR_PV + n * 65 + r] * sm[PR_RV + r];
            __nv_bfloat16 h = __float2bfloat16_rn(v);
            float lo = v - __bfloat162float(h);
            uint32_t off = jn * 16384 + SWZ((uint32_t)(n * 128 + r * 2));
            *(__nv_bfloat16*)((char*)g_Vbh + off) = h;
            *(__nv_bfloat16*)((char*)g_Vbl + off) = __float2bfloat16_rn(lo);
        }
    }
}

// ---------------------------------------------------------------------------
// Main kernel (R12 base). Phase 1: A quad-buffered, block barrier per 2 chunks
// (X is warp-private: per-thread cp wait + __syncwarp only).
// smem (96KB, 2 CTA/SM):
//   phase 1: [0,32768) warp-private X stage | [32768,98304) A bufs 0..3 (16K ea)
//   phase 2: three 32KB V buffers B0=[0,32K) B1=[32K,64K) B2=[64K,96K)
// ---------------------------------------------------------------------------
#define OFF_STAGE 0
#define OFF_A     32768
#define SMEM_BYTES 98304

__global__ __launch_bounds__(NTHREADS, 2) void k_gemm(const float* __restrict__ x,
                                                      float* __restrict__ out,
                                                      const float* __restrict__ sldj,
                                                      float* __restrict__ outSldj) {
    extern __shared__ char smem[];
    uint32_t sb = smem_to_u32(smem);

    int tid = threadIdx.x, wid = tid >> 5, lane = tid & 31;
    int m0 = blockIdx.x * TM;
    int mw = wid << 4;

    // B-side ldsm addressing (tiles with 128B rows, SW128)
    uint32_t lrow = lane & 15;
    uint32_t lcolb = (lane >> 4) << 4;
    uint32_t xwB = (lrow & 7) << 4;

    // A-side (warp-private fp32 stage)
    int r = lane >> 2;
    uint32_t rot = (uint32_t)(r & 7) << 5;
    uint32_t o3 = (uint32_t)(lane & 1) * 8;
    uint32_t sbStageW = sb + OFF_STAGE + wid * 4096;
    uint32_t rowbase = sbStageW + r * 256 + o3;
    int cpair = (lane >> 1) & 1;

    auto bufA = [&](int c) { return sb + OFF_A + (uint32_t)((c & 3) << 14); };
    auto issueA = [&](int c) {
        uint32_t buf = bufA(c);
        const char* srch = (const char*)g_Abh + c * 8192;
        const char* srcl = (const char*)g_Abl + c * 8192;
        for (int idx = tid; idx < 512; idx += NTHREADS) {
            cpasync16(buf + idx * 16, srch + idx * 16);
            cpasync16(buf + 8192 + idx * 16, srcl + idx * 16);
        }
    };
    auto issueXown = [&](int c) {
        #pragma unroll
        for (int u = 0; u < 8; u++) {
            int unit = lane + u * 32;
            int lr = unit >> 4, i16 = unit & 15;
            uint32_t dst = sbStageW + lr * 256 +
                           (((uint32_t)(i16 * 16)) ^ ((uint32_t)(lr & 7) << 5));
            const char* src = (const char*)(x + (size_t)(m0 + mw + lr) * Dv
                                            + c * 64 + i16 * 4);
            cpasync16(dst, src);
        }
    };
    auto issueV = [&](int j, uint32_t buf) {       // hi 16K at buf, lo 16K after
        const char* srch = (const char*)g_Vbh + j * 16384;
        const char* srcl = (const char*)g_Vbl + j * 16384;
        for (int idx = tid; idx < 1024; idx += NTHREADS) {
            cpasync16(buf + idx * 16, srch + idx * 16);
            cpasync16(buf + 16384 + idx * 16, srcl + idx * 16);
        }
    };

    float acc[8][4];
    #pragma unroll
    for (int i = 0; i < 8; i++)
        acc[i][0] = acc[i][1] = acc[i][2] = acc[i][3] = 0.f;

    // one-chunk compute (reads warp stage + A buffer)
    auto computeChunk = [&](int c) {
        uint32_t bufAh = bufA(c);
        uint32_t bufAl = bufAh + 8192;
        #pragma unroll
        for (int ks = 0; ks < 4; ks++) {
            int b0 = 4 * ks + cpair;
            uint32_t u0 = ((uint32_t)(b0 * 16)) ^ rot;
            uint32_t u1 = ((uint32_t)((b0 + 2) * 16)) ^ rot;
            float2 fa = lds64(rowbase + u0);
            float2 fb = lds64(rowbase + 2048 + u0);
            float2 fc = lds64(rowbase + u1);
            float2 fd = lds64(rowbase + 2048 + u1);
            uint32_t ah[4], al[4];
            ah[0] = cvt2(fa.x, fa.y); al[0] = cvt2(fa.x - bl(ah[0]), fa.y - bh(ah[0]));
            ah[1] = cvt2(fb.x, fb.y); al[1] = cvt2(fb.x - bl(ah[1]), fb.y - bh(ah[1]));
            ah[2] = cvt2(fc.x, fc.y); al[2] = cvt2(fc.x - bl(ah[2]), fc.y - bh(ah[2]));
            ah[3] = cvt2(fd.x, fd.y); al[3] = cvt2(fd.x - bl(ah[3]), fd.y - bh(ah[3]));

            uint32_t ic = (lcolb + ks * 32) ^ xwB;
            #pragma unroll
            for (int p = 0; p < 4; p++) {
                uint32_t ro = (lrow + p * 16) * 128;
                uint32_t bhr[4], blr[4];
                ldsm4(bhr, bufAh + ro + ic);
                ldsm4(blr, bufAl + ro + ic);
                mma16816(acc[2 * p],     ah, bhr[0], bhr[2]);
                mma16816(acc[2 * p],     ah, blr[0], blr[2]);
                mma16816(acc[2 * p],     al, bhr[0], bhr[2]);
                mma16816(acc[2 * p + 1], ah, bhr[1], bhr[3]);
                mma16816(acc[2 * p + 1], ah, blr[1], blr[3]);
                mma16816(acc[2 * p + 1], al, bhr[1], bhr[3]);
            }
        }
    };

    // prologue: X0 (group), A0+A1 (group)
    issueXown(0); CP_COMMIT();
    issueA(0); issueA(1); CP_COMMIT();

    // ====== Phase 1: 4 iterations x 2 chunks; block barrier once per iter ===
    #pragma unroll
    for (int cc = 0; cc < 4; cc++) {
        const int c0 = 2 * cc, c1 = c0 + 1;
        CP_WAIT(0);
        __syncthreads();                 // A(c0),A(c1) + X(c0) visible to all

        computeChunk(c0);

        issueXown(c1); CP_COMMIT();      // gX(c1)  (older than A pair below)
        if (cc < 3) { issueA(c0 + 2); issueA(c0 + 3); CP_COMMIT(); }

        if (cc < 3) { CP_WAIT(1); }      // gX(c1) done; A pair may pend
        else        { CP_WAIT(0); }
        __syncwarp();                    // warp-collective X(c1) visibility

        computeChunk(c1);

        if (cc < 3) { issueXown(c0 + 2); CP_COMMIT(); }
    }
    __syncthreads();                     // phase 1 fully done: all 96KB free

    // phase-2 prologue: V0,V1,V2 into B0,B1,B2
    issueV(0, sb + 0);     CP_COMMIT();
    issueV(1, sb + 32768); CP_COMMIT();
    issueV(2, sb + 65536); CP_COMMIT();

    // ======= Y: register repack acc (C-frag) -> phase-2 A-frags (hi/lo) =====
    uint32_t yh[4][4], yl[4][4];
    #pragma unroll
    for (int kb = 0; kb < 4; kb++) {
        uint32_t h;
        h = cvt2(acc[2*kb][0],   acc[2*kb][1]);   yh[kb][0] = h;
        yl[kb][0] = cvt2(acc[2*kb][0] - bl(h),    acc[2*kb][1] - bh(h));
        h = cvt2(acc[2*kb][2],   acc[2*kb][3]);   yh[kb][1] = h;
        yl[kb][1] = cvt2(acc[2*kb][2] - bl(h),    acc[2*kb][3] - bh(h));
        h = cvt2(acc[2*kb+1][0], acc[2*kb+1][1]); yh[kb][2] = h;
        yl[kb][2] = cvt2(acc[2*kb+1][0] - bl(h),  acc[2*kb+1][1] - bh(h));
        h = cvt2(acc[2*kb+1][2], acc[2*kb+1][3]); yh[kb][3] = h;
        yl[kb][3] = cvt2(acc[2*kb+1][2] - bl(h),  acc[2*kb+1][3] - bh(h));
    }

    // ====== Phase 2: Z = Y V^T, out = X - Z (4 n-chunks, 3-buffer rotate) ===
    const uint32_t vOff[4] = {0u, 32768u, 65536u, 0u};
    #pragma unroll
    for (int j = 0; j < 4; j++) {
        if (j <= 1)      CP_WAIT(2);
        else if (j == 2) CP_WAIT(1);
        else             CP_WAIT(0);
        __syncthreads();                 // collective visibility of V(j)
        uint32_t bufVh = sb + vOff[j], bufVl = bufVh + 16384;

        float z[16][4];
        #pragma unroll
        for (int i = 0; i < 16; i++)
            z[i][0] = z[i][1] = z[i][2] = z[i][3] = 0.f;

        #pragma unroll
        for (int ks = 0; ks < 4; ks++) {
            uint32_t ic = (lcolb + ks * 32) ^ xwB;
            #pragma unroll
            for (int p = 0; p < 8; p++) {
                uint32_t ro = (lrow + p * 16) * 128;
                uint32_t bhr[4], blr[4];
                ldsm4(bhr, bufVh + ro + ic);
                ldsm4(blr, bufVl + ro + ic);
                mma16816(z[2 * p],     yh[ks], bhr[0], bhr[2]);
                mma16816(z[2 * p],     yh[ks], blr[0], blr[2]);
                mma16816(z[2 * p],     yl[ks], bhr[0], bhr[2]);
                mma16816(z[2 * p + 1], yh[ks], bhr[1], bhr[3]);
                mma16816(z[2 * p + 1], yh[ks], blr[1], blr[3]);
                mma16816(z[2 * p + 1], yl[ks], bhr[1], bhr[3]);
            }
        }
        if (j == 0) {                    // B0 consumed by all -> host V3
            __syncthreads();
            issueV(3, sb + 0);
            CP_COMMIT();
        }

        // epilogue: out = x - z (fragment-mapped float2; x re-read hits L2)
        int r0 = m0 + mw + (lane >> 2);
        const float* x0p = x + (size_t)r0 * Dv;
        const float* x1p = x0p + 8 * Dv;
        float* o0 = out + (size_t)r0 * Dv;
        float* o1 = o0 + 8 * Dv;
        int cbase = (j << 7) + ((lane & 3) << 1);
        #pragma unroll
        for (int nt = 0; nt < 16; nt++) {
            int cc2 = cbase + nt * 8;
            float2 a0 = *(const float2*)(x0p + cc2);
            float2 a1 = *(const float2*)(x1p + cc2);
            float2 w0 = make_float2(a0.x - z[nt][0], a0.y - z[nt][1]);
            float2 w1 = make_float2(a1.x - z[nt][2], a1.y - z[nt][3]);
            *(float2*)(o0 + cc2) = w0;
            *(float2*)(o1 + cc2) = w1;
        }
    }

    if (outSldj != nullptr && tid < TM) {
        outSldj[m0 + tid] = sldj[m0 + tid];
    }
}

extern "C" void kernel_launch(void* const* d_in, const int* in_sizes, int n_in,
                              void* d_out, int out_size) {
    const float* x    = (const float*)d_in[0];   // (B, D)
    const float* sldj = (const float*)d_in[1];   // (B,)
    const float* P    = (const float*)d_in[2];   // (D, R)
    int BD = in_sizes[0];
    int Bn = in_sizes[1];
    (void)n_in;
    float* out = (float*)d_out;
    float* osl = (out_size >= BD + Bn) ? (out + BD) : nullptr;

    k_gram<<<256, 256>>>(P);
    cudaFuncSetAttribute(k_pack, cudaFuncAttributeMaxDynamicSharedMemorySize,
                         PR_FLOATS * 4);
    k_pack<<<12, 512, PR_FLOATS * 4>>>(P);

    cudaFuncSetAttribute(k_gemm, cudaFuncAttributeMaxDynamicSharedMemorySize, SMEM_BYTES);
    k_gemm<<<Bn / TM, NTHREADS, SMEM_BYTES>>>(x, out, sldj, osl);
}

// round 15
// speedup vs baseline: 1.0487x; 1.0081x over previous
#include <cuda_runtime.h>
#include <cuda_bf16.h>
#include <cstdint>

#define Dv 512
#define Rv 64
#define TM 128
#define NTHREADS 256

// ---------------------------------------------------------------------------
// Device scratch
// ---------------------------------------------------------------------------
__device__ float g_G0p[4 * 4096];  // Gram partials (4 d-quarters)
// Pre-packed bf16 hi/lo operand tiles, 128B rows, SW128-swizzled
__device__ __align__(16) __nv_bfloat16 g_Abh[8 * 64 * 64];   // chunk c: [r][kk]
__device__ __align__(16) __nv_bfloat16 g_Abl[8 * 64 * 64];
__device__ __align__(16) __nv_bfloat16 g_Vbh[4 * 128 * 64];  // n-chunk j: [n][r]
__device__ __align__(16) __nv_bfloat16 g_Vbl[4 * 128 * 64];
// Y fragments between phases: [cta*8+wid][group 0..7][lane][4 words]
__device__ __align__(16) uint32_t g_Y[512 * 8 * 8 * 128];    // 16 MB

// ---------------------------------------------------------------------------
// Helpers
// ---------------------------------------------------------------------------
#define SWZ(o) ((o) ^ (((o) >> 3) & 0x70))

__device__ __forceinline__ uint32_t smem_to_u32(const void* p) {
    uint32_t a;
    asm("{ .reg .u64 t; cvta.to.shared.u64 t, %1; cvt.u32.u64 %0, t; }" : "=r"(a) : "l"(p));
    return a;
}
__device__ __forceinline__ void ldsm4(uint32_t* r, uint32_t addr) {
    asm volatile("ldmatrix.sync.aligned.m8n8.x4.shared.b16 {%0,%1,%2,%3}, [%4];"
                 : "=r"(r[0]), "=r"(r[1]), "=r"(r[2]), "=r"(r[3]) : "r"(addr));
}
__device__ __forceinline__ void mma16816(float* c, const uint32_t* a,
                                         uint32_t b0, uint32_t b1) {
    asm volatile("mma.sync.aligned.m16n8k16.row.col.f32.bf16.bf16.f32 "
                 "{%0,%1,%2,%3}, {%4,%5,%6,%7}, {%8,%9}, {%0,%1,%2,%3};"
                 : "+f"(c[0]), "+f"(c[1]), "+f"(c[2]), "+f"(c[3])
                 : "r"(a[0]), "r"(a[1]), "r"(a[2]), "r"(a[3]), "r"(b0), "r"(b1));
}
__device__ __forceinline__ float2 lds64(uint32_t a) {
    float2 v;
    asm volatile("ld.shared.v2.f32 {%0,%1}, [%2];" : "=f"(v.x), "=f"(v.y) : "r"(a));
    return v;
}
__device__ __forceinline__ void cpasync16(uint32_t dst, const void* src) {
    asm volatile("cp.async.cg.shared.global [%0], [%1], 16;"
                 :: "r"(dst), "l"(src) : "memory");
}
#define CP_COMMIT() asm volatile("cp.async.commit_group;" ::: "memory")
#define CP_WAIT(N)  asm volatile("cp.async.wait_group %0;" :: "n"(N) : "memory")

__device__ __forceinline__ uint32_t cvt2(float f0, float f1) {
    uint32_t r;
    asm("cvt.rn.bf16x2.f32 %0, %1, %2;" : "=r"(r) : "f"(f1), "f"(f0));
    return r;
}
__device__ __forceinline__ float bl(uint32_t h) { return __uint_as_float(h << 16); }
__device__ __forceinline__ float bh(uint32_t h) { return __uint_as_float(h & 0xFFFF0000u); }

// ---------------------------------------------------------------------------
// Precompute 1: Gram partials. 256 blocks (64 j x 4 d-quarters) x 256 thr.
// ---------------------------------------------------------------------------
__global__ __launch_bounds__(256) void k_gram(const float* __restrict__ P) {
    __shared__ float red[4][64];
    int bid = blockIdx.x;
    int j = bid & 63, q = bid >> 6;
    int k = threadIdx.x & 63, g = threadIdx.x >> 6;
    const float* p = P + (q * 128 + g * 32) * 64;
    float a[8] = {};
    #pragma unroll
    for (int d = 0; d < 32; d += 8) {
        #pragma unroll
        for (int e = 0; e < 8; e++)
            a[e] += __ldg(p + (d + e) * 64 + j) * __ldg(p + (d + e) * 64 + k);
    }
    red[g][k] = ((a[0] + a[1]) + (a[2] + a[3])) + ((a[4] + a[5]) + (a[6] + a[7]));
    __syncthreads();
    if (g == 0)
        g_G0p[q * 4096 + j * 64 + k] =
            (red[0][k] + red[1][k]) + (red[2][k] + red[3][k]);
}

// ---------------------------------------------------------------------------
// Precompute 2: 12 blocks x 512 thr (scan back-sub, validated R11-R14).
// ---------------------------------------------------------------------------
#define PR_RV  0            // 64
#define PR_M   64           // 64*65
#define PR_W2  4224         // 64*65
#define PR_SP  8384         // 64*68
#define PR_PV  64           // 128*65 (V path overlaps M/W2)
#define PR_FLOATS 12736

__global__ __launch_bounds__(512) void k_pack(const float* __restrict__ P) {
    extern __shared__ float sm[];
    int bid = blockIdx.x, tid = threadIdx.x, w = tid >> 5, lane = tid & 31;

    if (tid < 64) {
        float s = g_G0p[tid * 65] + g_G0p[4096 + tid * 65]
                + g_G0p[8192 + tid * 65] + g_G0p[12288 + tid * 65];
        sm[PR_RV + tid] = rsqrtf(s);
    }
    __syncthreads();

    if (bid < 8) {
        int c = bid;
        for (int idx = tid; idx < 4096; idx += 512) {
            int i = idx >> 6, l = idx & 63;
            float gv = g_G0p[idx] + g_G0p[4096 + idx]
                     + g_G0p[8192 + idx] + g_G0p[12288 + idx];
            sm[PR_M + i * 65 + l] = 2.f * gv * sm[PR_RV + i] * sm[PR_RV + l];
        }
        for (int idx = tid; idx < 4096; idx += 512)
            sm[PR_SP + (idx >> 6) * 68 + (idx & 63)] = P[c * 4096 + idx];
        __syncthreads();

        // scan back-substitution: warp w solves cols {w, w+16, w+32, w+48}
        {
            float S0[4] = {0.f, 0.f, 0.f, 0.f};
            float S1[4] = {0.f, 0.f, 0.f, 0.f};
            float wv0[4] = {0.f, 0.f, 0.f, 0.f};
            float wv1[4] = {0.f, 0.f, 0.f, 0.f};
            for (int i = 63; i >= 0; --i) {
                float m0 = sm[PR_M + i * 65 + lane];
                float m1 = sm[PR_M + i * 65 + lane + 32];
                #pragma unroll
                for (int q = 0; q < 4; q++) {
                    int cq = w + 16 * q;
                    float sown = (i < 32) ? S0[q] : S1[q];
                    float s_i = __shfl_sync(0xFFFFFFFFu, sown, i & 31);
                    float wi = (i > cq) ? 0.f : ((i == cq) ? 1.f : -s_i);
                    if (lane == i)      wv0[q] = wi;
                    if (lane + 32 == i) wv1[q] = wi;
                    if (lane < i)       S0[q] += m0 * wi;
                    if (lane + 32 < i)  S1[q] += m1 * wi;
                }
            }
            #pragma unroll
            for (int q = 0; q < 4; q++) {
                int cq = w + 16 * q;
                sm[PR_W2 + lane * 65 + cq]        = 2.f * sm[PR_RV + lane] * wv0[q];
                sm[PR_W2 + (lane + 32) * 65 + cq] = 2.f * sm[PR_RV + lane + 32] * wv1[q];
            }
        }
        __syncthreads();

        int rr = tid & 63, kb = (tid >> 6) << 3;
        float pacc[8] = {};
        #pragma unroll 4
        for (int jj = 0; jj < 64; jj++) {
            float wv = sm[PR_W2 + jj * 65 + rr];
            #pragma unroll
            for (int e = 0; e < 8; e++)
                pacc[e] += sm[PR_SP + (kb + e) * 68 + jj] * wv;
        }
        #pragma unroll
        for (int e = 0; e < 8; e++) {
            float v = pacc[e];
            __nv_bfloat16 h = __float2bfloat16_rn(v);
            float lo = v - __bfloat162float(h);
            uint32_t off = c * 8192 + SWZ((uint32_t)(rr * 128 + (kb + e) * 2));
            *(__nv_bfloat16*)((char*)g_Abh + off) = h;
            *(__nv_bfloat16*)((char*)g_Abl + off) = __float2bfloat16_rn(lo);
        }
    } else {
        int jn = bid - 8;
        for (int idx = tid; idx < 8192; idx += 512)
            sm[PR_PV + (idx >> 6) * 65 + (idx & 63)] = P[jn * 8192 + idx];
        __syncthreads();
        for (int idx = tid; idx < 8192; idx += 512) {
            int n = idx >> 6, r = idx & 63;
            float v = sm[PR_PV + n * 65 + r] * sm[PR_RV + r];
            __nv_bfloat16 h = __float2bfloat16_rn(v);
            float lo = v - __bfloat162float(h);
            uint32_t off = jn * 16384 + SWZ((uint32_t)(n * 128 + r * 2));
            *(__nv_bfloat16*)((char*)g_Vbh + off) = h;
            *(__nv_bfloat16*)((char*)g_Vbl + off) = __float2bfloat16_rn(lo);
        }
    }
}

// ---------------------------------------------------------------------------
// Phase-1 kernel: Y = X A, fragments -> g_Y. 64KB smem, 3 CTA/SM.
//   [0,32768)  warp-private fp32 X stage (4KB/warp)
//   [32768,65536) A ping/pong (16K each)
// ---------------------------------------------------------------------------
#define P1_OFF_A 32768
#define P1_SMEM  65536

__global__ __launch_bounds__(NTHREADS, 3) void k_p1(const float* __restrict__ x) {
    extern __shared__ char smem[];
    uint32_t sb = smem_to_u32(smem);

    int tid = threadIdx.x, wid = tid >> 5, lane = tid & 31;
    int m0 = blockIdx.x * TM;
    int mw = wid << 4;

    uint32_t lrow = lane & 15;
    uint32_t lcolb = (lane >> 4) << 4;
    uint32_t xwB = (lrow & 7) << 4;

    int r = lane >> 2;
    uint32_t rot = (uint32_t)(r & 7) << 5;
    uint32_t o3 = (uint32_t)(lane & 1) * 8;
    uint32_t sbStageW = sb + wid * 4096;
    uint32_t rowbase = sbStageW + r * 256 + o3;
    int cpair = (lane >> 1) & 1;

    auto issueA = [&](int c, uint32_t buf) {
        const char* srch = (const char*)g_Abh + c * 8192;
        const char* srcl = (const char*)g_Abl + c * 8192;
        for (int idx = tid; idx < 512; idx += NTHREADS) {
            cpasync16(buf + idx * 16, srch + idx * 16);
            cpasync16(buf + 8192 + idx * 16, srcl + idx * 16);
        }
    };
    auto issueXown = [&](int c) {
        #pragma unroll
        for (int u = 0; u < 8; u++) {
            int unit = lane + u * 32;
            int lr = unit >> 4, i16 = unit & 15;
            uint32_t dst = sbStageW + lr * 256 +
                           (((uint32_t)(i16 * 16)) ^ ((uint32_t)(lr & 7) << 5));
            const char* src = (const char*)(x + (size_t)(m0 + mw + lr) * Dv
                                            + c * 64 + i16 * 4);
            cpasync16(dst, src);
        }
    };

    float acc[8][4];
    #pragma unroll
    for (int i = 0; i < 8; i++)
        acc[i][0] = acc[i][1] = acc[i][2] = acc[i][3] = 0.f;

    issueXown(0);
    issueA(0, sb + P1_OFF_A);
    CP_COMMIT();

    for (int c = 0; c < 8; c++) {
        CP_WAIT(0);
        __syncthreads();
        if (c < 7) {
            issueA(c + 1, sb + P1_OFF_A + (uint32_t)(((c + 1) & 1) << 14));
            CP_COMMIT();
        }
        uint32_t bufAh = sb + P1_OFF_A + (uint32_t)((c & 1) << 14);
        uint32_t bufAl = bufAh + 8192;
        #pragma unroll
        for (int ks = 0; ks < 4; ks++) {
            int b0 = 4 * ks + cpair;
            uint32_t u0 = ((uint32_t)(b0 * 16)) ^ rot;
            uint32_t u1 = ((uint32_t)((b0 + 2) * 16)) ^ rot;
            float2 fa = lds64(rowbase + u0);
            float2 fb = lds64(rowbase + 2048 + u0);
            float2 fc = lds64(rowbase + u1);
            float2 fd = lds64(rowbase + 2048 + u1);
            uint32_t ah[4], al[4];
            ah[0] = cvt2(fa.x, fa.y); al[0] = cvt2(fa.x - bl(ah[0]), fa.y - bh(ah[0]));
            ah[1] = cvt2(fb.x, fb.y); al[1] = cvt2(fb.x - bl(ah[1]), fb.y - bh(ah[1]));
            ah[2] = cvt2(fc.x, fc.y); al[2] = cvt2(fc.x - bl(ah[2]), fc.y - bh(ah[2]));
            ah[3] = cvt2(fd.x, fd.y); al[3] = cvt2(fd.x - bl(ah[3]), fd.y - bh(ah[3]));

            uint32_t ic = (lcolb + ks * 32) ^ xwB;
            #pragma unroll
            for (int p = 0; p < 4; p++) {
                uint32_t ro = (lrow + p * 16) * 128;
                uint32_t bhr[4], blr[4];
                ldsm4(bhr, bufAh + ro + ic);
                ldsm4(blr, bufAl + ro + ic);
                mma16816(acc[2 * p],     ah, bhr[0], bhr[2]);
                mma16816(acc[2 * p],     ah, blr[0], blr[2]);
                mma16816(acc[2 * p],     al, bhr[0], bhr[2]);
                mma16816(acc[2 * p + 1], ah, bhr[1], bhr[3]);
                mma16816(acc[2 * p + 1], ah, blr[1], blr[3]);
                mma16816(acc[2 * p + 1], al, bhr[1], bhr[3]);
            }
        }
        if (c < 7) { issueXown(c + 1); CP_COMMIT(); }
    }

    // pack acc -> Y fragments (hi groups 0-3, lo groups 4-7), coalesced STG.128
    char* ybase = (char*)g_Y
        + ((size_t)(blockIdx.x * 8 + wid) * 8) * 512 + (uint32_t)lane * 16;
    #pragma unroll
    for (int kb = 0; kb < 4; kb++) {
        uint32_t h0 = cvt2(acc[2*kb][0],   acc[2*kb][1]);
        uint32_t l0 = cvt2(acc[2*kb][0] - bl(h0),   acc[2*kb][1] - bh(h0));
        uint32_t h1 = cvt2(acc[2*kb][2],   acc[2*kb][3]);
        uint32_t l1 = cvt2(acc[2*kb][2] - bl(h1),   acc[2*kb][3] - bh(h1));
        uint32_t h2 = cvt2(acc[2*kb+1][0], acc[2*kb+1][1]);
        uint32_t l2 = cvt2(acc[2*kb+1][0] - bl(h2), acc[2*kb+1][1] - bh(h2));
        uint32_t h3 = cvt2(acc[2*kb+1][2], acc[2*kb+1][3]);
        uint32_t l3 = cvt2(acc[2*kb+1][2] - bl(h3), acc[2*kb+1][3] - bh(h3));
        *(uint4*)(ybase + (size_t)kb * 512)       = make_uint4(h0, h1, h2, h3);
        *(uint4*)(ybase + (size_t)(kb + 4) * 512) = make_uint4(l0, l1, l2, l3);
    }
}

// ---------------------------------------------------------------------------
// Phase-2 kernel: out = X - Y V^T. 96KB smem, 2 CTA/SM, 3-buffer V rotate.
// ---------------------------------------------------------------------------
#define P2_SMEM 98304

__global__ __launch_bounds__(NTHREADS, 2) void k_p2(const float* __restrict__ x,
                                                    float* __restrict__ out,
                                                    const float* __restrict__ sldj,
                                                    float* __restrict__ outSldj) {
    extern __shared__ char smem[];
    uint32_t sb = smem_to_u32(smem);

    int tid = threadIdx.x, wid = tid >> 5, lane = tid & 31;
    int m0 = blockIdx.x * TM;
    int mw = wid << 4;

    uint32_t lrow = lane & 15;
    uint32_t lcolb = (lane >> 4) << 4;
    uint32_t xwB = (lrow & 7) << 4;

    auto issueV = [&](int j, uint32_t buf) {
        const char* srch = (const char*)g_Vbh + j * 16384;
        const char* srcl = (const char*)g_Vbl + j * 16384;
        for (int idx = tid; idx < 1024; idx += NTHREADS) {
            cpasync16(buf + idx * 16, srch + idx * 16);
            cpasync16(buf + 16384 + idx * 16, srcl + idx * 16);
        }
    };

    // V pipeline fill starts immediately
    issueV(0, sb + 0);     CP_COMMIT();
    issueV(1, sb + 32768); CP_COMMIT();
    issueV(2, sb + 65536); CP_COMMIT();

    // load Y fragments (coalesced LDG.128), overlaps the cp.async fill
    uint32_t yh[4][4], yl[4][4];
    {
        const char* ybase = (const char*)g_Y
            + ((size_t)(blockIdx.x * 8 + wid) * 8) * 512 + (uint32_t)lane * 16;
        #pragma unroll
        for (int kb = 0; kb < 4; kb++) {
            uint4 vh = *(const uint4*)(ybase + (size_t)kb * 512);
            uint4 vl = *(const uint4*)(ybase + (size_t)(kb + 4) * 512);
            yh[kb][0] = vh.x; yh[kb][1] = vh.y; yh[kb][2] = vh.z; yh[kb][3] = vh.w;
            yl[kb][0] = vl.x; yl[kb][1] = vl.y; yl[kb][2] = vl.z; yl[kb][3] = vl.w;
        }
    }

    const uint32_t vOff[4] = {0u, 32768u, 65536u, 0u};
    #pragma unroll
    for (int j = 0; j < 4; j++) {
        if (j <= 1)      CP_WAIT(2);
        else if (j == 2) CP_WAIT(1);
        else             CP_WAIT(0);
        __syncthreads();
        uint32_t bufVh = sb + vOff[j], bufVl = bufVh + 16384;

        float z[16][4];
        #pragma unroll
        for (int i = 0; i < 16; i++)
            z[i][0] = z[i][1] = z[i][2] = z[i][3] = 0.f;

        #pragma unroll
        for (int ks = 0; ks < 4; ks++) {
            uint32_t ic = (lcolb + ks * 32) ^ xwB;
            #pragma unroll
            for (int p = 0; p < 8; p++) {
                uint32_t ro = (lrow + p * 16) * 128;
                uint32_t bhr[4], blr[4];
                ldsm4(bhr, bufVh + ro + ic);
                ldsm4(blr, bufVl + ro + ic);
                mma16816(z[2 * p],     yh[ks], bhr[0], bhr[2]);
                mma16816(z[2 * p],     yh[ks], blr[0], blr[2]);
                mma16816(z[2 * p],     yl[ks], bhr[0], bhr[2]);
                mma16816(z[2 * p + 1], yh[ks], bhr[1], bhr[3]);
                mma16816(z[2 * p + 1], yh[ks], blr[1], blr[3]);
                mma16816(z[2 * p + 1], yl[ks], bhr[1], bhr[3]);
            }
        }
        if (j == 0) {
            __syncthreads();
            issueV(3, sb + 0);
            CP_COMMIT();
        }

        int r0 = m0 + mw + (lane >> 2);
        const float* x0p = x + (size_t)r0 * Dv;
        const float* x1p = x0p + 8 * Dv;
        float* o0 = out + (size_t)r0 * Dv;
        float* o1 = o0 + 8 * Dv;
        int cbase = (j << 7) + ((lane & 3) << 1);
        #pragma unroll
        for (int nt = 0; nt < 16; nt++) {
            int cc2 = cbase + nt * 8;
            float2 a0 = *(const float2*)(x0p + cc2);
            float2 a1 = *(const float2*)(x1p + cc2);
            float2 w0 = make_float2(a0.x - z[nt][0], a0.y - z[nt][1]);
            float2 w1 = make_float2(a1.x - z[nt][2], a1.y - z[nt][3]);
            *(float2*)(o0 + cc2) = w0;
            *(float2*)(o1 + cc2) = w1;
        }
    }

    if (outSldj != nullptr && tid < TM) {
        outSldj[m0 + tid] = sldj[m0 + tid];
    }
}

extern "C" void kernel_launch(void* const* d_in, const int* in_sizes, int n_in,
                              void* d_out, int out_size) {
    const float* x    = (const float*)d_in[0];   // (B, D)
    const float* sldj = (const float*)d_in[1];   // (B,)
    const float* P    = (const float*)d_in[2];   // (D, R)
    int BD = in_sizes[0];
    int Bn = in_sizes[1];
    (void)n_in;
    float* out = (float*)d_out;
    float* osl = (out_size >= BD + Bn) ? (out + BD) : nullptr;

    k_gram<<<256, 256>>>(P);
    cudaFuncSetAttribute(k_pack, cudaFuncAttributeMaxDynamicSharedMemorySize,
                         PR_FLOATS * 4);
    k_pack<<<12, 512, PR_FLOATS * 4>>>(P);

    cudaFuncSetAttribute(k_p1, cudaFuncAttributeMaxDynamicSharedMemorySize, P1_SMEM);
    k_p1<<<Bn / TM, NTHREADS, P1_SMEM>>>(x);

    cudaFuncSetAttribute(k_p2, cudaFuncAttributeMaxDynamicSharedMemorySize, P2_SMEM);
    k_p2<<<Bn / TM, NTHREADS, P2_SMEM>>>(x, out, sldj, osl);
}